// round 10
// baseline (speedup 1.0000x reference)
#include <cuda_runtime.h>
#include <cstdint>

#define BATCH    256
#define IN_DIM   512
#define OUT_DIM  512
#define NWORK    512
#define TOPK     154

// ------------------- persistent device scratch (no runtime allocation) -------------------
__device__ int   d_count[NWORK];                        // tokens per expert
__device__ int   d_tok[NWORK * 256];                    // token id per (expert, row)
__device__ float d_wt [NWORK * 256];                    // gate weight per (expert, row)
__device__ int   d_dst[NWORK * 256];                    // staging row (= b*TOPK + slot)
__device__ int   d_tokcnt[BATCH];                       // slot counter per token
__device__ float d_ystage[BATCH * TOPK * OUT_DIM];      // 77 MB staging: [token, slot, out]

// ------------------- helpers (baseline compute_103 PTX only) -------------------
__device__ __forceinline__ uint32_t smem_u32(const void* p) {
    uint32_t a;
    asm("{ .reg .u64 t; cvta.to.shared.u64 t, %1; cvt.u32.u64 %0, t; }" : "=r"(a) : "l"(p));
    return a;
}
#define SWZ(o) ((o) ^ (((o) >> 3) & 0x70))

__device__ __forceinline__ void ldm_x4(uint32_t* r, uint32_t addr) {
    asm volatile("ldmatrix.sync.aligned.m8n8.x4.shared.b16 {%0,%1,%2,%3}, [%4];"
                 : "=r"(r[0]), "=r"(r[1]), "=r"(r[2]), "=r"(r[3]) : "r"(addr));
}

__device__ __forceinline__ void mma_bf16(float* d, const uint32_t* a, const uint32_t* b) {
    asm volatile("mma.sync.aligned.m16n8k16.row.col.f32.bf16.bf16.f32 "
                 "{%0,%1,%2,%3}, {%4,%5,%6,%7}, {%8,%9}, {%0,%1,%2,%3};"
                 : "+f"(d[0]), "+f"(d[1]), "+f"(d[2]), "+f"(d[3])
                 : "r"(a[0]), "r"(a[1]), "r"(a[2]), "r"(a[3]), "r"(b[0]), "r"(b[1]));
}

__device__ __forceinline__ void sts128(uint32_t addr, uint4 v) {
    asm volatile("st.shared.v4.b32 [%0], {%1, %2, %3, %4};"
                 :: "r"(addr), "r"(v.x), "r"(v.y), "r"(v.z), "r"(v.w) : "memory");
}

// split 8 f32 -> bf16 hi plane (rn) + bf16 lo plane (rn of exact residual)
__device__ __forceinline__ void cvt8(const float* f, uint4& hi, uint4& lo) {
    uint32_t h[4], l[4];
#pragma unroll
    for (int j = 0; j < 4; j++) {
        float a = f[2 * j], b = f[2 * j + 1];
        uint32_t hp;
        asm("cvt.rn.bf16x2.f32 %0, %1, %2;" : "=r"(hp) : "f"(b), "f"(a));  // lo half = a
        float ra = a - __uint_as_float(hp << 16);
        float rb = b - __uint_as_float(hp & 0xFFFF0000u);
        uint32_t lp;
        asm("cvt.rn.bf16x2.f32 %0, %1, %2;" : "=r"(lp) : "f"(rb), "f"(ra));
        h[j] = hp; l[j] = lp;
    }
    hi = make_uint4(h[0], h[1], h[2], h[3]);
    lo = make_uint4(l[0], l[1], l[2], l[3]);
}

// ------------------- kernel 0: zero counters -------------------
__global__ void zero_kernel() {
    int i = threadIdx.x;
    if (i < NWORK) d_count[i] = 0;
    if (i < BATCH) d_tokcnt[i] = 0;
}

// ------------------- kernel 1: router -------------------
// 4 tokens/block, thread e = expert. Exact top-154 via radix threshold search.
__global__ void __launch_bounds__(512) router_kernel(const float* __restrict__ x,
                                                     const float* __restrict__ gw,
                                                     const float* __restrict__ gb) {
    __shared__ __align__(16) float sx[4][IN_DIM];
    __shared__ float sred[512];
    const int e  = threadIdx.x;
    const int b0 = blockIdx.x * 4;

    for (int i = e; i < 4 * IN_DIM; i += 512) sx[i >> 9][i & 511] = x[b0 * IN_DIM + i];
    __syncthreads();

    float bias = gb[e];
    float acc[4] = {bias, bias, bias, bias};
    const float4* g4 = (const float4*)(gw + (size_t)e * IN_DIM);
#pragma unroll 4
    for (int k = 0; k < IN_DIM / 4; k++) {
        float4 g = g4[k];
#pragma unroll
        for (int t = 0; t < 4; t++) {
            float4 xv = ((const float4*)sx[t])[k];
            acc[t] += g.x * xv.x + g.y * xv.y + g.z * xv.z + g.w * xv.w;
        }
    }

    for (int t = 0; t < 4; t++) {
        const int b = b0 + t;
        const float l = acc[t];
        uint32_t u = __float_as_uint(l);
        u = (u & 0x80000000u) ? ~u : (u | 0x80000000u);   // order-preserving map

        uint32_t res = 0;                                  // K-th largest threshold
        for (int bit = 31; bit >= 0; bit--) {
            uint32_t cand = res | (1u << bit);
            int c = __syncthreads_count(u >= cand);
            if (c >= TOPK) res = cand;
        }
        const bool sel = (u >= res);

        sred[e] = l;
        __syncthreads();
        for (int s = 256; s; s >>= 1) { if (e < s) sred[e] = fmaxf(sred[e], sred[e + s]); __syncthreads(); }
        const float lmax = sred[0];
        __syncthreads();

        const float ex = sel ? __expf(l - lmax) : 0.f;
        sred[e] = ex;
        __syncthreads();
        for (int s = 256; s; s >>= 1) { if (e < s) sred[e] += sred[e + s]; __syncthreads(); }
        const float wsum = sred[0];
        __syncthreads();

        if (sel) {
            float w = ex / wsum;
            int r = atomicAdd(&d_count[e], 1);
            int j = atomicAdd(&d_tokcnt[b], 1);
            if (r < 256 && j < TOPK) {
                d_tok[e * 256 + r] = b;
                d_wt [e * 256 + r] = w;
                d_dst[e * 256 + r] = b * TOPK + j;
            }
        }
        __syncthreads();
    }
}

// ------------------- kernel 2: grouped GEMM (mma.sync HMMA, split-bf16 x3) -------------------
// grid (expert 512, n-quarter 4, m-chunk 2), 256 thr, 2 CTAs/SM.
// Warp w owns M-strip [16w, 16w+16); warps past `rows` skip MMA (M-skip).
#define SM_TOK  0
#define SM_WT   512
#define SM_DST  1024
#define SM_AHI  2048
#define SM_ALO  (2048 + 16384)
#define SM_BHI  (2048 + 32768)
#define SM_BLO  (2048 + 49152)
#define SMEM_BYTES (2048 + 65536)   /* 67584 B */

__global__ void __launch_bounds__(256, 2)
moe_gemm(const float* __restrict__ x, const float* __restrict__ tiles) {
    extern __shared__ char smem[];
    const int e  = blockIdx.x;
    const int nq = blockIdx.y;          // N-quarter: cols [nq*128, nq*128+128)
    const int mc = blockIdx.z;
    const int cnt  = d_count[e];
    const int rows = min(128, cnt - mc * 128);
    if (rows <= 0) return;

    const uint32_t sb  = smem_u32(smem);
    const int tid = threadIdx.x, wid = tid >> 5, lid = tid & 31;
    const int m0 = wid * 16;

    if (tid < 128) {
        int r = tid;
        bool valid = r < rows;
        int idx = e * 256 + mc * 128 + r;
        ((int*)  (smem + SM_TOK))[r] = valid ? d_tok[idx] : 0;
        ((float*)(smem + SM_WT ))[r] = valid ? d_wt [idx] : 0.f;
        ((int*)  (smem + SM_DST))[r] = valid ? d_dst[idx] : 0;
    }
    __syncthreads();

    // ldmatrix lane address components
    const int ar  = (lid & 7) + ((lid >> 3) & 1) * 8;   // A: row within strip
    const int akb = ((lid >> 4) & 1) * 16;              // A: k-byte offset
    const int br  = (lid & 7) + ((lid >> 4) & 1) * 8;   // B: n within 16-group
    const int bkb = ((lid >> 3) & 1) * 16;              // B: k-byte offset

    float acc[16][4];
#pragma unroll
    for (int t = 0; t < 16; t++)
#pragma unroll
        for (int j = 0; j < 4; j++) acc[t][j] = 0.f;

    const float* tbase = tiles + ((size_t)e * OUT_DIM + nq * 128) * IN_DIM;

    for (int kc = 0; kc < 8; kc++) {
        // A chunk: 128 rows x 64 cols (weight-scaled gathered tokens)
        for (int i = tid; i < 1024; i += 256) {
            int r = i >> 3, g = i & 7;
            int tok = ((int*)  (smem + SM_TOK))[r];
            float w = ((float*)(smem + SM_WT ))[r];
            const float4* p = (const float4*)(x + (size_t)tok * IN_DIM + kc * 64 + g * 8);
            float4 v0 = p[0], v1 = p[1];
            float f[8] = {w*v0.x, w*v0.y, w*v0.z, w*v0.w, w*v1.x, w*v1.y, w*v1.z, w*v1.w};
            uint4 hi, lo; cvt8(f, hi, lo);
            uint32_t off = SWZ((uint32_t)(r * 128 + g * 16));
            sts128(sb + SM_AHI + off, hi);
            sts128(sb + SM_ALO + off, lo);
        }
        // B chunk: 128 tile rows x 64 cols
        for (int i = tid; i < 1024; i += 256) {
            int r = i >> 3, g = i & 7;
            const float4* p = (const float4*)(tbase + (size_t)r * IN_DIM + kc * 64 + g * 8);
            float4 v0 = p[0], v1 = p[1];
            float f[8] = {v0.x, v0.y, v0.z, v0.w, v1.x, v1.y, v1.z, v1.w};
            uint4 hi, lo; cvt8(f, hi, lo);
            uint32_t off = SWZ((uint32_t)(r * 128 + g * 16));
            sts128(sb + SM_BHI + off, hi);
            sts128(sb + SM_BLO + off, lo);
        }
        __syncthreads();

        if (m0 < rows) {                       // M-skip: idle warps do no MMA work
#pragma unroll
            for (int ks = 0; ks < 4; ks++) {
                uint32_t a_hi[4], a_lo[4];
                uint32_t aoff = SWZ((uint32_t)((m0 + ar) * 128 + 32 * ks + akb));
                ldm_x4(a_hi, sb + SM_AHI + aoff);
                ldm_x4(a_lo, sb + SM_ALO + aoff);
#pragma unroll
                for (int np = 0; np < 8; np++) {           // pairs of n-tiles
                    uint32_t boff = SWZ((uint32_t)((np * 16 + br) * 128 + 32 * ks + bkb));
                    uint32_t b_hi[4], b_lo[4];
                    ldm_x4(b_hi, sb + SM_BHI + boff);
                    ldm_x4(b_lo, sb + SM_BLO + boff);
                    mma_bf16(acc[2*np],     a_hi, b_hi);
                    mma_bf16(acc[2*np],     a_hi, b_lo);
                    mma_bf16(acc[2*np],     a_lo, b_hi);
                    mma_bf16(acc[2*np + 1], a_hi, b_hi + 2);
                    mma_bf16(acc[2*np + 1], a_hi, b_lo + 2);
                    mma_bf16(acc[2*np + 1], a_lo, b_hi + 2);
                }
            }
        }
        __syncthreads();
    }

    // epilogue: d-frag rows m0 + lid/4 and +8; cols t*8 + 2*(lid%4) + {0,1}
    if (m0 < rows) {
        const int mA = m0 + (lid >> 2);
        const int mB = mA + 8;
        const bool vA = mA < rows, vB = mB < rows;
        const int dA = vA ? ((int*)(smem + SM_DST))[mA] : 0;
        const int dB = vB ? ((int*)(smem + SM_DST))[mB] : 0;
        float* oA = d_ystage + (size_t)dA * OUT_DIM + nq * 128;
        float* oB = d_ystage + (size_t)dB * OUT_DIM + nq * 128;
        const int nb = 2 * (lid & 3);
#pragma unroll
        for (int t = 0; t < 16; t++) {
            int n = t * 8 + nb;
            if (vA) *(float2*)(oA + n) = make_float2(acc[t][0], acc[t][1]);
            if (vB) *(float2*)(oB + n) = make_float2(acc[t][2], acc[t][3]);
        }
    }
}

// ------------------- kernel 3: per-token reduction over 154 staged rows -------------------
__global__ void __launch_bounds__(256) reduce_kernel(float* __restrict__ out) {
    const int b    = blockIdx.x >> 1;
    const int half = blockIdx.x & 1;
    const int c    = half * 256 + threadIdx.x;
    const float* base = d_ystage + (size_t)b * TOPK * OUT_DIM + c;
    float acc = 0.f;
#pragma unroll 7
    for (int j = 0; j < TOPK; j++) acc += base[(size_t)j * OUT_DIM];
    out[b * OUT_DIM + c] = acc;
}

// ------------------- launcher -------------------
extern "C" void kernel_launch(void* const* d_in, const int* in_sizes, int n_in,
                              void* d_out, int out_size) {
    const float* x     = (const float*)d_in[0];
    const float* gw    = (const float*)d_in[1];
    const float* gb    = (const float*)d_in[2];
    const float* tiles = (const float*)d_in[3];
    float* out = (float*)d_out;

    zero_kernel<<<1, 512>>>();
    router_kernel<<<BATCH / 4, 512>>>(x, gw, gb);
    cudaFuncSetAttribute(moe_gemm, cudaFuncAttributeMaxDynamicSharedMemorySize, SMEM_BYTES);
    moe_gemm<<<dim3(NWORK, 4, 2), 256, SMEM_BYTES>>>(x, tiles);
    reduce_kernel<<<BATCH * 2, 256>>>(out);
}

// round 11
// speedup vs baseline: 1.3985x; 1.3985x over previous
#include <cuda_runtime.h>
#include <cuda_fp16.h>
#include <cstdint>

#define BATCH    256
#define IN_DIM   512
#define OUT_DIM  512
#define NWORK    512
#define TOPK     154

// ------------------- persistent device scratch (no runtime allocation) -------------------
__device__ int   d_count[NWORK];                        // tokens per expert
__device__ int   d_tok[NWORK * 256];                    // token id per (expert, row)
__device__ float d_wt [NWORK * 256];                    // gate weight per (expert, row)
__device__ int   d_dst[NWORK * 256];                    // staging row (= b*TOPK + slot)
__device__ int   d_tokcnt[BATCH];                       // slot counter per token
__device__ float d_ystage[BATCH * TOPK * OUT_DIM];      // 77 MB staging: [token, slot, out]

// ------------------- helpers (baseline compute_103 PTX only) -------------------
__device__ __forceinline__ uint32_t smem_u32(const void* p) {
    uint32_t a;
    asm("{ .reg .u64 t; cvta.to.shared.u64 t, %1; cvt.u32.u64 %0, t; }" : "=r"(a) : "l"(p));
    return a;
}
#define SWZ(o) ((o) ^ (((o) >> 3) & 0x70))

__device__ __forceinline__ void ldm_x4(uint32_t* r, uint32_t addr) {
    asm volatile("ldmatrix.sync.aligned.m8n8.x4.shared.b16 {%0,%1,%2,%3}, [%4];"
                 : "=r"(r[0]), "=r"(r[1]), "=r"(r[2]), "=r"(r[3]) : "r"(addr));
}

__device__ __forceinline__ void mma_fp16(float* d, const uint32_t* a, const uint32_t* b) {
    asm volatile("mma.sync.aligned.m16n8k16.row.col.f32.f16.f16.f32 "
                 "{%0,%1,%2,%3}, {%4,%5,%6,%7}, {%8,%9}, {%0,%1,%2,%3};"
                 : "+f"(d[0]), "+f"(d[1]), "+f"(d[2]), "+f"(d[3])
                 : "r"(a[0]), "r"(a[1]), "r"(a[2]), "r"(a[3]), "r"(b[0]), "r"(b[1]));
}

__device__ __forceinline__ void sts128(uint32_t addr, uint4 v) {
    asm volatile("st.shared.v4.b32 [%0], {%1, %2, %3, %4};"
                 :: "r"(addr), "r"(v.x), "r"(v.y), "r"(v.z), "r"(v.w) : "memory");
}

__device__ __forceinline__ uint32_t pack_h2(float a, float b) {
    __half2 h = __floats2half2_rn(a, b);          // .x (low half) = a
    return *reinterpret_cast<uint32_t*>(&h);
}

// 8 f32 -> fp16 hi plane + fp16 residual-lo plane
__device__ __forceinline__ void cvt8_split(const float* f, uint4& hi, uint4& lo) {
    uint32_t h[4], l[4];
#pragma unroll
    for (int j = 0; j < 4; j++) {
        float a = f[2 * j], b = f[2 * j + 1];
        __half2 hh = __floats2half2_rn(a, b);
        h[j] = *reinterpret_cast<uint32_t*>(&hh);
        float ra = a - __half2float(__low2half(hh));
        float rb = b - __half2float(__high2half(hh));
        l[j] = pack_h2(ra, rb);
    }
    hi = make_uint4(h[0], h[1], h[2], h[3]);
    lo = make_uint4(l[0], l[1], l[2], l[3]);
}

// 8 f32 -> fp16 single plane
__device__ __forceinline__ uint4 cvt8_single(const float* f) {
    return make_uint4(pack_h2(f[0], f[1]), pack_h2(f[2], f[3]),
                      pack_h2(f[4], f[5]), pack_h2(f[6], f[7]));
}

// ------------------- kernel 0: zero counters -------------------
__global__ void zero_kernel() {
    int i = threadIdx.x;
    if (i < NWORK) d_count[i] = 0;
    if (i < BATCH) d_tokcnt[i] = 0;
}

// ------------------- kernel 1: router -------------------
__global__ void __launch_bounds__(512) router_kernel(const float* __restrict__ x,
                                                     const float* __restrict__ gw,
                                                     const float* __restrict__ gb) {
    __shared__ __align__(16) float sx[4][IN_DIM];
    __shared__ float sred[512];
    const int e  = threadIdx.x;
    const int b0 = blockIdx.x * 4;

    for (int i = e; i < 4 * IN_DIM; i += 512) sx[i >> 9][i & 511] = x[b0 * IN_DIM + i];
    __syncthreads();

    float bias = gb[e];
    float acc[4] = {bias, bias, bias, bias};
    const float4* g4 = (const float4*)(gw + (size_t)e * IN_DIM);
#pragma unroll 4
    for (int k = 0; k < IN_DIM / 4; k++) {
        float4 g = g4[k];
#pragma unroll
        for (int t = 0; t < 4; t++) {
            float4 xv = ((const float4*)sx[t])[k];
            acc[t] += g.x * xv.x + g.y * xv.y + g.z * xv.z + g.w * xv.w;
        }
    }

    for (int t = 0; t < 4; t++) {
        const int b = b0 + t;
        const float l = acc[t];
        uint32_t u = __float_as_uint(l);
        u = (u & 0x80000000u) ? ~u : (u | 0x80000000u);   // order-preserving map

        uint32_t res = 0;                                  // K-th largest threshold
        for (int bit = 31; bit >= 0; bit--) {
            uint32_t cand = res | (1u << bit);
            int c = __syncthreads_count(u >= cand);
            if (c >= TOPK) res = cand;
        }
        const bool sel = (u >= res);

        sred[e] = l;
        __syncthreads();
        for (int s = 256; s; s >>= 1) { if (e < s) sred[e] = fmaxf(sred[e], sred[e + s]); __syncthreads(); }
        const float lmax = sred[0];
        __syncthreads();

        const float ex = sel ? __expf(l - lmax) : 0.f;
        sred[e] = ex;
        __syncthreads();
        for (int s = 256; s; s >>= 1) { if (e < s) sred[e] += sred[e + s]; __syncthreads(); }
        const float wsum = sred[0];
        __syncthreads();

        if (sel) {
            float w = ex / wsum;
            int r = atomicAdd(&d_count[e], 1);
            int j = atomicAdd(&d_tokcnt[b], 1);
            if (r < 256 && j < TOPK) {
                d_tok[e * 256 + r] = b;
                d_wt [e * 256 + r] = w;
                d_dst[e * 256 + r] = b * TOPK + j;
            }
        }
        __syncthreads();
    }
}

// ------------------- kernel 2: grouped GEMM (HMMA fp16 2-term, double-buffered) -------------------
// grid (expert 512, n-quarter 4, m-chunk 2), 256 thr, 2 CTAs/SM.
// A = x tokens (no weight) split fp16 hi+lo; B = tile rows single fp16; w applied in epilogue.
#define SM_TOK   0
#define SM_WT    512
#define SM_DST   1024
#define SM_BUF   2048
#define BUF_SZ   49152           /* A_hi 16K + A_lo 16K + B 16K */
#define A_HI_OFF 0
#define A_LO_OFF 16384
#define B_OFF    32768
#define SMEM_BYTES (2048 + 2 * BUF_SZ)   /* 100352 B */

__global__ void __launch_bounds__(256, 2)
moe_gemm(const float* __restrict__ x, const float* __restrict__ tiles) {
    extern __shared__ char smem[];
    const int e  = blockIdx.x;
    const int nq = blockIdx.y;          // N-quarter: cols [nq*128, nq*128+128)
    const int mc = blockIdx.z;
    const int cnt  = d_count[e];
    const int rows = min(128, cnt - mc * 128);
    if (rows <= 0) return;

    const uint32_t sb  = smem_u32(smem);
    const int tid = threadIdx.x, wid = tid >> 5, lid = tid & 31;
    const int m0 = wid * 16;

    if (tid < 128) {
        int r = tid;
        bool valid = r < rows;
        int idx = e * 256 + mc * 128 + r;
        ((int*)  (smem + SM_TOK))[r] = valid ? d_tok[idx] : 0;
        ((float*)(smem + SM_WT ))[r] = valid ? d_wt [idx] : 0.f;
        ((int*)  (smem + SM_DST))[r] = valid ? d_dst[idx] : 0;
    }
    __syncthreads();

    // ldmatrix lane address components (validated in R10)
    const int ar  = (lid & 7) + ((lid >> 3) & 1) * 8;   // A: row within strip
    const int akb = ((lid >> 4) & 1) * 16;              // A: k-byte offset
    const int br  = (lid & 7) + ((lid >> 4) & 1) * 8;   // B: n within 16-group
    const int bkb = ((lid >> 3) & 1) * 16;              // B: k-byte offset

    float acc[16][4];
#pragma unroll
    for (int t = 0; t < 16; t++)
#pragma unroll
        for (int j = 0; j < 4; j++) acc[t][j] = 0.f;

    const float* tbase = tiles + ((size_t)e * OUT_DIM + nq * 128) * IN_DIM;

    // ---- fill stage: convert chunk kc into buffer `bufb` ----
    auto fill = [&](int kc, uint32_t bufb) {
        // A chunk: 128 rows x 64 cols of raw x (no weight), split hi/lo
#pragma unroll
        for (int it = 0; it < 4; it++) {
            int i = tid + it * 256;
            int r = i >> 3, g = i & 7;
            int tok = ((int*)(smem + SM_TOK))[r];
            const float4* p = (const float4*)(x + (size_t)tok * IN_DIM + kc * 64 + g * 8);
            float4 v0 = p[0], v1 = p[1];
            float f[8] = {v0.x, v0.y, v0.z, v0.w, v1.x, v1.y, v1.z, v1.w};
            uint4 hi, lo; cvt8_split(f, hi, lo);
            uint32_t off = SWZ((uint32_t)(r * 128 + g * 16));
            sts128(bufb + A_HI_OFF + off, hi);
            sts128(bufb + A_LO_OFF + off, lo);
        }
        // B chunk: 128 tile rows x 64 cols, single fp16
#pragma unroll
        for (int it = 0; it < 4; it++) {
            int i = tid + it * 256;
            int r = i >> 3, g = i & 7;
            const float4* p = (const float4*)(tbase + (size_t)r * IN_DIM + kc * 64 + g * 8);
            float4 v0 = p[0], v1 = p[1];
            float f[8] = {v0.x, v0.y, v0.z, v0.w, v1.x, v1.y, v1.z, v1.w};
            uint32_t off = SWZ((uint32_t)(r * 128 + g * 16));
            sts128(bufb + B_OFF + off, cvt8_single(f));
        }
    };

    fill(0, sb + SM_BUF);
    __syncthreads();

    for (int kc = 0; kc < 8; kc++) {
        const uint32_t cur = sb + SM_BUF + (uint32_t)(kc & 1) * BUF_SZ;

        if (m0 < rows) {                       // M-skip: idle warps go prefetch next chunk
#pragma unroll
            for (int ks = 0; ks < 4; ks++) {
                uint32_t a_hi[4], a_lo[4];
                uint32_t aoff = SWZ((uint32_t)((m0 + ar) * 128 + 32 * ks + akb));
                ldm_x4(a_hi, cur + A_HI_OFF + aoff);
                ldm_x4(a_lo, cur + A_LO_OFF + aoff);
#pragma unroll
                for (int np = 0; np < 8; np++) {
                    uint32_t b[4];
                    uint32_t boff = SWZ((uint32_t)((np * 16 + br) * 128 + 32 * ks + bkb));
                    ldm_x4(b, cur + B_OFF + boff);
                    // RAW distance-2 interleave across the two accumulators
                    mma_fp16(acc[2*np],     a_hi, b);
                    mma_fp16(acc[2*np + 1], a_hi, b + 2);
                    mma_fp16(acc[2*np],     a_lo, b);
                    mma_fp16(acc[2*np + 1], a_lo, b + 2);
                }
            }
        }
        if (kc < 7) {
            fill(kc + 1, sb + SM_BUF + (uint32_t)((kc + 1) & 1) * BUF_SZ);
            __syncthreads();   // one barrier per chunk: fill(k+1) done, mma(k) done everywhere
        }
    }

    // epilogue: rows mA = m0 + lid/4, mB = mA + 8; apply gate weight here
    if (m0 < rows) {
        const int mA = m0 + (lid >> 2);
        const int mB = mA + 8;
        const bool vA = mA < rows, vB = mB < rows;
        const int dA = vA ? ((int*)(smem + SM_DST))[mA] : 0;
        const int dB = vB ? ((int*)(smem + SM_DST))[mB] : 0;
        const float wA = vA ? ((float*)(smem + SM_WT))[mA] : 0.f;
        const float wB = vB ? ((float*)(smem + SM_WT))[mB] : 0.f;
        float* oA = d_ystage + (size_t)dA * OUT_DIM + nq * 128;
        float* oB = d_ystage + (size_t)dB * OUT_DIM + nq * 128;
        const int nb = 2 * (lid & 3);
#pragma unroll
        for (int t = 0; t < 16; t++) {
            int n = t * 8 + nb;
            if (vA) *(float2*)(oA + n) = make_float2(wA * acc[t][0], wA * acc[t][1]);
            if (vB) *(float2*)(oB + n) = make_float2(wB * acc[t][2], wB * acc[t][3]);
        }
    }
}

// ------------------- kernel 3: per-token reduction over 154 staged rows -------------------
__global__ void __launch_bounds__(256) reduce_kernel(float* __restrict__ out) {
    const int b    = blockIdx.x >> 1;
    const int half = blockIdx.x & 1;
    const int c    = half * 256 + threadIdx.x;
    const float* base = d_ystage + (size_t)b * TOPK * OUT_DIM + c;
    float a0 = 0.f, a1 = 0.f, a2 = 0.f, a3 = 0.f;
    int j = 0;
#pragma unroll 4
    for (; j + 4 <= TOPK; j += 4) {            // 152 iterations, 4-way MLP
        a0 += base[(size_t)(j + 0) * OUT_DIM];
        a1 += base[(size_t)(j + 1) * OUT_DIM];
        a2 += base[(size_t)(j + 2) * OUT_DIM];
        a3 += base[(size_t)(j + 3) * OUT_DIM];
    }
    for (; j < TOPK; j++) a0 += base[(size_t)j * OUT_DIM];
    out[b * OUT_DIM + c] = (a0 + a1) + (a2 + a3);
}

// ------------------- launcher -------------------
extern "C" void kernel_launch(void* const* d_in, const int* in_sizes, int n_in,
                              void* d_out, int out_size) {
    const float* x     = (const float*)d_in[0];
    const float* gw    = (const float*)d_in[1];
    const float* gb    = (const float*)d_in[2];
    const float* tiles = (const float*)d_in[3];
    float* out = (float*)d_out;

    zero_kernel<<<1, 512>>>();
    router_kernel<<<BATCH / 4, 512>>>(x, gw, gb);
    cudaFuncSetAttribute(moe_gemm, cudaFuncAttributeMaxDynamicSharedMemorySize, SMEM_BYTES);
    moe_gemm<<<dim3(NWORK, 4, 2), 256, SMEM_BYTES>>>(x, tiles);
    reduce_kernel<<<BATCH * 2, 256>>>(out);
}

// round 12
// speedup vs baseline: 1.6803x; 1.2014x over previous
#include <cuda_runtime.h>
#include <cuda_fp16.h>
#include <cstdint>

#define BATCH    256
#define IN_DIM   512
#define OUT_DIM  512
#define NWORK    512
#define TOPK     154

// ------------------- persistent device scratch (no runtime allocation) -------------------
__device__ int   d_count[NWORK];                        // tokens per expert
__device__ int   d_tok[NWORK * 256];                    // token id per (expert, row)
__device__ float d_wt [NWORK * 256];                    // gate weight per (expert, row)
__device__ int   d_dst[NWORK * 256];                    // staging row (= b*TOPK + slot)
__device__ int   d_tokcnt[BATCH];                       // slot counter per token
__device__ float d_ystage[BATCH * TOPK * OUT_DIM];      // 77 MB staging: [token, slot, out]

// ------------------- helpers (baseline compute_103 PTX only) -------------------
__device__ __forceinline__ uint32_t smem_u32(const void* p) {
    uint32_t a;
    asm("{ .reg .u64 t; cvta.to.shared.u64 t, %1; cvt.u32.u64 %0, t; }" : "=r"(a) : "l"(p));
    return a;
}
#define SWZ(o) ((o) ^ (((o) >> 3) & 0x70))

__device__ __forceinline__ void ldm_x4(uint32_t* r, uint32_t addr) {
    asm volatile("ldmatrix.sync.aligned.m8n8.x4.shared.b16 {%0,%1,%2,%3}, [%4];"
                 : "=r"(r[0]), "=r"(r[1]), "=r"(r[2]), "=r"(r[3]) : "r"(addr));
}

__device__ __forceinline__ void mma_fp16(float* d, const uint32_t* a, const uint32_t* b) {
    asm volatile("mma.sync.aligned.m16n8k16.row.col.f32.f16.f16.f32 "
                 "{%0,%1,%2,%3}, {%4,%5,%6,%7}, {%8,%9}, {%0,%1,%2,%3};"
                 : "+f"(d[0]), "+f"(d[1]), "+f"(d[2]), "+f"(d[3])
                 : "r"(a[0]), "r"(a[1]), "r"(a[2]), "r"(a[3]), "r"(b[0]), "r"(b[1]));
}

__device__ __forceinline__ void sts128(uint32_t addr, uint4 v) {
    asm volatile("st.shared.v4.b32 [%0], {%1, %2, %3, %4};"
                 :: "r"(addr), "r"(v.x), "r"(v.y), "r"(v.z), "r"(v.w) : "memory");
}

__device__ __forceinline__ uint32_t pack_h2(float a, float b) {
    __half2 h = __floats2half2_rn(a, b);          // .x (low half) = a
    return *reinterpret_cast<uint32_t*>(&h);
}

// 2x float4 -> fp16x8 (single-rounded plane)
__device__ __forceinline__ uint4 cvt8_single(float4 v0, float4 v1) {
    return make_uint4(pack_h2(v0.x, v0.y), pack_h2(v0.z, v0.w),
                      pack_h2(v1.x, v1.y), pack_h2(v1.z, v1.w));
}

// ------------------- kernel 0: zero counters -------------------
__global__ void zero_kernel() {
    int i = threadIdx.x;
    if (i < NWORK) d_count[i] = 0;
    if (i < BATCH) d_tokcnt[i] = 0;
}

// ------------------- kernel 1: router -------------------
__global__ void __launch_bounds__(512) router_kernel(const float* __restrict__ x,
                                                     const float* __restrict__ gw,
                                                     const float* __restrict__ gb) {
    __shared__ __align__(16) float sx[4][IN_DIM];
    __shared__ float sred[512];
    const int e  = threadIdx.x;
    const int b0 = blockIdx.x * 4;

    for (int i = e; i < 4 * IN_DIM; i += 512) sx[i >> 9][i & 511] = x[b0 * IN_DIM + i];
    __syncthreads();

    float bias = gb[e];
    float acc[4] = {bias, bias, bias, bias};
    const float4* g4 = (const float4*)(gw + (size_t)e * IN_DIM);
#pragma unroll 4
    for (int k = 0; k < IN_DIM / 4; k++) {
        float4 g = g4[k];
#pragma unroll
        for (int t = 0; t < 4; t++) {
            float4 xv = ((const float4*)sx[t])[k];
            acc[t] += g.x * xv.x + g.y * xv.y + g.z * xv.z + g.w * xv.w;
        }
    }

    for (int t = 0; t < 4; t++) {
        const int b = b0 + t;
        const float l = acc[t];
        uint32_t u = __float_as_uint(l);
        u = (u & 0x80000000u) ? ~u : (u | 0x80000000u);   // order-preserving map

        uint32_t res = 0;                                  // K-th largest threshold
        for (int bit = 31; bit >= 0; bit--) {
            uint32_t cand = res | (1u << bit);
            int c = __syncthreads_count(u >= cand);
            if (c >= TOPK) res = cand;
        }
        const bool sel = (u >= res);

        sred[e] = l;
        __syncthreads();
        for (int s = 256; s; s >>= 1) { if (e < s) sred[e] = fmaxf(sred[e], sred[e + s]); __syncthreads(); }
        const float lmax = sred[0];
        __syncthreads();

        const float ex = sel ? __expf(l - lmax) : 0.f;
        sred[e] = ex;
        __syncthreads();
        for (int s = 256; s; s >>= 1) { if (e < s) sred[e] += sred[e + s]; __syncthreads(); }
        const float wsum = sred[0];
        __syncthreads();

        if (sel) {
            float w = ex / wsum;
            int r = atomicAdd(&d_count[e], 1);
            int j = atomicAdd(&d_tokcnt[b], 1);
            if (r < 256 && j < TOPK) {
                d_tok[e * 256 + r] = b;
                d_wt [e * 256 + r] = w;
                d_dst[e * 256 + r] = b * TOPK + j;
            }
        }
        __syncthreads();
    }
}

// ------------------- kernel 2: grouped GEMM (HMMA fp16 single-plane, B reg-prefetch) -------------------
// grid (expert 512, n-quarter 4, m-chunk 2), 256 thr, 2 CTAs/SM.
// A = x tokens fp16 (no weight); B = tile rows fp16; gate weight applied in epilogue.
#define SM_TOK   0
#define SM_WT    512
#define SM_DST   1024
#define SM_BUF   2048
#define BUF_SZ   32768           /* A 16K + B 16K */
#define A_OFF    0
#define B_OFF    16384
#define SMEM_BYTES (2048 + 2 * BUF_SZ)   /* 67584 B */

__global__ void __launch_bounds__(256, 2)
moe_gemm(const float* __restrict__ x, const float* __restrict__ tiles) {
    extern __shared__ char smem[];
    const int e  = blockIdx.x;
    const int nq = blockIdx.y;          // N-quarter: cols [nq*128, nq*128+128)
    const int mc = blockIdx.z;
    const int cnt  = d_count[e];
    const int rows = min(128, cnt - mc * 128);
    if (rows <= 0) return;

    const uint32_t sb  = smem_u32(smem);
    const int tid = threadIdx.x, wid = tid >> 5, lid = tid & 31;
    const int m0 = wid * 16;

    if (tid < 128) {
        int r = tid;
        bool valid = r < rows;
        int idx = e * 256 + mc * 128 + r;
        ((int*)  (smem + SM_TOK))[r] = valid ? d_tok[idx] : 0;
        ((float*)(smem + SM_WT ))[r] = valid ? d_wt [idx] : 0.f;
        ((int*)  (smem + SM_DST))[r] = valid ? d_dst[idx] : 0;
    }
    __syncthreads();

    // ldmatrix lane address components (validated in R10)
    const int ar  = (lid & 7) + ((lid >> 3) & 1) * 8;   // A: row within strip
    const int akb = ((lid >> 4) & 1) * 16;              // A: k-byte offset
    const int br  = (lid & 7) + ((lid >> 4) & 1) * 8;   // B: n within 16-group
    const int bkb = ((lid >> 3) & 1) * 16;              // B: k-byte offset

    float acc[16][4];
#pragma unroll
    for (int t = 0; t < 16; t++)
#pragma unroll
        for (int j = 0; j < 4; j++) acc[t][j] = 0.f;

    const float* tbase = tiles + ((size_t)e * OUT_DIM + nq * 128) * IN_DIM;
    const int fr = tid >> 3, fg = tid & 7;              // this thread's fill (row, group)
    const uint32_t foff = SWZ((uint32_t)(fr * 128 + fg * 16));
    const int ftok = ((int*)(smem + SM_TOK))[fr];       // A gather token for fill rows

    float4 pf[8];                                        // B prefetch registers (2 per 32-row band)

    // ---- B: issue 8 LDG.128 for chunk kc into pf ----
    auto loadB = [&](int kc) {
#pragma unroll
        for (int it = 0; it < 4; it++) {
            const float4* p = (const float4*)(tbase + (size_t)(fr + 32 * it) * IN_DIM + kc * 64 + fg * 8);
            pf[2 * it]     = p[0];
            pf[2 * it + 1] = p[1];
        }
    };
    // ---- B: convert prefetched regs into buffer ----
    auto storeB = [&](uint32_t bufb) {
#pragma unroll
        for (int it = 0; it < 4; it++) {
            uint32_t off = SWZ((uint32_t)((fr + 32 * it) * 128 + fg * 16));
            sts128(bufb + B_OFF + off, cvt8_single(pf[2 * it], pf[2 * it + 1]));
        }
    };
    // ---- A: gather + convert + store (x is L2-resident) ----
    auto fillA = [&](int kc, uint32_t bufb) {
#pragma unroll
        for (int it = 0; it < 4; it++) {
            int r = fr + 32 * it;
            int tok = ((int*)(smem + SM_TOK))[r];
            const float4* p = (const float4*)(x + (size_t)tok * IN_DIM + kc * 64 + fg * 8);
            float4 v0 = p[0], v1 = p[1];
            uint32_t off = SWZ((uint32_t)(r * 128 + fg * 16));
            sts128(bufb + A_OFF + off, cvt8_single(v0, v1));
        }
    };
    (void)ftok; (void)foff;

    // prologue: stage chunk 0
    loadB(0);
    storeB(sb + SM_BUF);
    fillA(0, sb + SM_BUF);
    __syncthreads();

    for (int kc = 0; kc < 8; kc++) {
        const uint32_t cur = sb + SM_BUF + (uint32_t)(kc & 1) * BUF_SZ;

        if (kc < 7) loadB(kc + 1);             // DRAM LDGs in flight across the MMA phase

        if (m0 < rows) {                       // M-skip: warps past `rows` act as producers only
#pragma unroll
            for (int ks = 0; ks < 4; ks++) {
                uint32_t a[4];
                uint32_t aoff = SWZ((uint32_t)((m0 + ar) * 128 + 32 * ks + akb));
                ldm_x4(a, cur + A_OFF + aoff);
#pragma unroll
                for (int np = 0; np < 8; np++) {
                    uint32_t b[4];
                    uint32_t boff = SWZ((uint32_t)((np * 16 + br) * 128 + 32 * ks + bkb));
                    ldm_x4(b, cur + B_OFF + boff);
                    mma_fp16(acc[2 * np],     a, b);
                    mma_fp16(acc[2 * np + 1], a, b + 2);
                }
            }
        }

        if (kc < 7) {
            const uint32_t nxt = sb + SM_BUF + (uint32_t)((kc + 1) & 1) * BUF_SZ;
            storeB(nxt);
            fillA(kc + 1, nxt);
            __syncthreads();                   // one barrier per chunk
        }
    }

    // epilogue: rows mA = m0 + lid/4, mB = mA + 8; apply gate weight here
    if (m0 < rows) {
        const int mA = m0 + (lid >> 2);
        const int mB = mA + 8;
        const bool vA = mA < rows, vB = mB < rows;
        const int dA = vA ? ((int*)(smem + SM_DST))[mA] : 0;
        const int dB = vB ? ((int*)(smem + SM_DST))[mB] : 0;
        const float wA = vA ? ((float*)(smem + SM_WT))[mA] : 0.f;
        const float wB = vB ? ((float*)(smem + SM_WT))[mB] : 0.f;
        float* oA = d_ystage + (size_t)dA * OUT_DIM + nq * 128;
        float* oB = d_ystage + (size_t)dB * OUT_DIM + nq * 128;
        const int nb = 2 * (lid & 3);
#pragma unroll
        for (int t = 0; t < 16; t++) {
            int n = t * 8 + nb;
            if (vA) *(float2*)(oA + n) = make_float2(wA * acc[t][0], wA * acc[t][1]);
            if (vB) *(float2*)(oB + n) = make_float2(wB * acc[t][2], wB * acc[t][3]);
        }
    }
}

// ------------------- kernel 3: per-token reduction over 154 staged rows -------------------
__global__ void __launch_bounds__(256) reduce_kernel(float* __restrict__ out) {
    const int b    = blockIdx.x >> 1;
    const int half = blockIdx.x & 1;
    const int c    = half * 256 + threadIdx.x;
    const float* base = d_ystage + (size_t)b * TOPK * OUT_DIM + c;
    float a0 = 0.f, a1 = 0.f, a2 = 0.f, a3 = 0.f;
    float a4 = 0.f, a5 = 0.f, a6 = 0.f, a7 = 0.f;
    int j = 0;
    for (; j + 8 <= TOPK; j += 8) {            // 8-way MLP
        a0 += base[(size_t)(j + 0) * OUT_DIM];
        a1 += base[(size_t)(j + 1) * OUT_DIM];
        a2 += base[(size_t)(j + 2) * OUT_DIM];
        a3 += base[(size_t)(j + 3) * OUT_DIM];
        a4 += base[(size_t)(j + 4) * OUT_DIM];
        a5 += base[(size_t)(j + 5) * OUT_DIM];
        a6 += base[(size_t)(j + 6) * OUT_DIM];
        a7 += base[(size_t)(j + 7) * OUT_DIM];
    }
    for (; j < TOPK; j++) a0 += base[(size_t)j * OUT_DIM];
    out[b * OUT_DIM + c] = ((a0 + a1) + (a2 + a3)) + ((a4 + a5) + (a6 + a7));
}

// ------------------- launcher -------------------
extern "C" void kernel_launch(void* const* d_in, const int* in_sizes, int n_in,
                              void* d_out, int out_size) {
    const float* x     = (const float*)d_in[0];
    const float* gw    = (const float*)d_in[1];
    const float* gb    = (const float*)d_in[2];
    const float* tiles = (const float*)d_in[3];
    float* out = (float*)d_out;

    zero_kernel<<<1, 512>>>();
    router_kernel<<<BATCH / 4, 512>>>(x, gw, gb);
    cudaFuncSetAttribute(moe_gemm, cudaFuncAttributeMaxDynamicSharedMemorySize, SMEM_BYTES);
    moe_gemm<<<dim3(NWORK, 4, 2), 256, SMEM_BYTES>>>(x, tiles);
    reduce_kernel<<<BATCH * 2, 256>>>(out);
}